// round 1
// baseline (speedup 1.0000x reference)
#include <cuda_runtime.h>
#include <math.h>

#define N_NODES 8192
#define DIM     512
#define TOPK_K  20

#define NEG_INF __int_as_float(0xff800000)

// ---------------- device scratch (static globals, no runtime alloc) --------
__device__ float g_Q[(size_t)N_NODES * DIM];
__device__ float g_K[(size_t)N_NODES * DIM];
__device__ float g_logits[(size_t)N_NODES * N_NODES];

// ---------------------------------------------------------------------------
// C[M,N] = alpha * A[M,K] @ B[N,K]^T   (+ prior_scale*prior, diag -> -inf)
// Classic SGEMM: 128x128 block tile, BK=8, 8x8 per-thread microtile, 256 thr.
// ---------------------------------------------------------------------------
template <bool ADD_PRIOR>
__global__ void __launch_bounds__(256, 2)
gemm_nt_kernel(const float* __restrict__ A, const float* __restrict__ B,
               float* __restrict__ C, const float* __restrict__ prior,
               const float* __restrict__ prior_scale,
               int M, int N, int K, float alpha)
{
    constexpr int BM = 128, BN = 128, BK = 8, TM = 8, TN = 8;
    __shared__ float As[BK * BM];   // transposed: As[k][m]
    __shared__ float Bs[BK * BN];   // transposed: Bs[k][n]

    const int tid  = threadIdx.x;
    const int brow = blockIdx.y;
    const int bcol = blockIdx.x;

    const float* Ab = A + (size_t)brow * BM * K;
    const float* Bb = B + (size_t)bcol * BN * K;

    const int trow = tid / 16;          // 0..15 -> rows trow*8..+7
    const int tcol = tid % 16;          // 0..15 -> cols tcol*8..+7

    const int innerRow = tid / 2;       // 0..127
    const int innerCol = tid % 2;       // which float4 along K

    float acc[TM][TN] = {};
    float regM[TM], regN[TN];

    for (int kt = 0; kt < K; kt += BK) {
        float4 a4 = *(const float4*)(Ab + (size_t)innerRow * K + kt + innerCol * 4);
        float4 b4 = *(const float4*)(Bb + (size_t)innerRow * K + kt + innerCol * 4);
        As[(innerCol * 4 + 0) * BM + innerRow] = a4.x;
        As[(innerCol * 4 + 1) * BM + innerRow] = a4.y;
        As[(innerCol * 4 + 2) * BM + innerRow] = a4.z;
        As[(innerCol * 4 + 3) * BM + innerRow] = a4.w;
        Bs[(innerCol * 4 + 0) * BN + innerRow] = b4.x;
        Bs[(innerCol * 4 + 1) * BN + innerRow] = b4.y;
        Bs[(innerCol * 4 + 2) * BN + innerRow] = b4.z;
        Bs[(innerCol * 4 + 3) * BN + innerRow] = b4.w;
        __syncthreads();

        #pragma unroll
        for (int k = 0; k < BK; k++) {
            #pragma unroll
            for (int i = 0; i < TM; i++) regM[i] = As[k * BM + trow * TM + i];
            #pragma unroll
            for (int j = 0; j < TN; j++) regN[j] = Bs[k * BN + tcol * TN + j];
            #pragma unroll
            for (int i = 0; i < TM; i++)
                #pragma unroll
                for (int j = 0; j < TN; j++)
                    acc[i][j] += regM[i] * regN[j];
        }
        __syncthreads();
    }

    float ps = 0.0f;
    if (ADD_PRIOR) ps = prior_scale[0];

    #pragma unroll
    for (int i = 0; i < TM; i++) {
        const int gm = brow * BM + trow * TM + i;
        #pragma unroll
        for (int j = 0; j < TN; j += 4) {
            const int gn = bcol * BN + tcol * TN + j;
            float4 r;
            r.x = acc[i][j + 0] * alpha;
            r.y = acc[i][j + 1] * alpha;
            r.z = acc[i][j + 2] * alpha;
            r.w = acc[i][j + 3] * alpha;
            if (ADD_PRIOR) {
                const float4 p4 = *(const float4*)(prior + (size_t)gm * N + gn);
                r.x += ps * p4.x;
                r.y += ps * p4.y;
                r.z += ps * p4.z;
                r.w += ps * p4.w;
                if (gm == gn + 0) r.x = NEG_INF;
                if (gm == gn + 1) r.y = NEG_INF;
                if (gm == gn + 2) r.z = NEG_INF;
                if (gm == gn + 3) r.w = NEG_INF;
            }
            *(float4*)(C + (size_t)gm * N + gn) = r;
        }
    }
}

// ---------------------------------------------------------------------------
// Per-row top-20 + softmax + full-row write (zeros + sparse scatter).
// One block (256 threads) per row; row lives in registers (32 floats/thread).
// 20 iterations of block-wide argmax extraction.
// ---------------------------------------------------------------------------
__global__ void __launch_bounds__(256)
topk_softmax_kernel(const float* __restrict__ logits, float* __restrict__ out)
{
    const int row = blockIdx.x;
    const int t   = threadIdx.x;
    const float* lrow = logits + (size_t)row * N_NODES;

    float v[32];
    #pragma unroll
    for (int i = 0; i < 32; i++)
        v[i] = lrow[t + 256 * i];      // diagonal already -inf from GEMM epilogue

    __shared__ float s_val[8];
    __shared__ int   s_idx[8];
    __shared__ float topv[TOPK_K];
    __shared__ int   topi[TOPK_K];
    __shared__ int   s_winner;

    for (int it = 0; it < TOPK_K; it++) {
        // local argmax over this thread's 32 elements
        float bv = NEG_INF;
        int   bi = 0;
        #pragma unroll
        for (int i = 0; i < 32; i++)
            if (v[i] > bv) { bv = v[i]; bi = i; }
        int bj = t + 256 * bi;

        // warp argmax
        #pragma unroll
        for (int o = 16; o > 0; o >>= 1) {
            float ov = __shfl_down_sync(0xffffffffu, bv, o);
            int   oj = __shfl_down_sync(0xffffffffu, bj, o);
            if (ov > bv) { bv = ov; bj = oj; }
        }
        if ((t & 31) == 0) { s_val[t >> 5] = bv; s_idx[t >> 5] = bj; }
        __syncthreads();

        if (t == 0) {
            float best = s_val[0]; int bidx = s_idx[0];
            #pragma unroll
            for (int w = 1; w < 8; w++)
                if (s_val[w] > best) { best = s_val[w]; bidx = s_idx[w]; }
            topv[it]  = best;
            topi[it]  = bidx;
            s_winner  = bidx;
        }
        __syncthreads();

        const int widx = s_winner;
        if ((widx & 255) == t) v[widx >> 8] = NEG_INF;
        // no extra sync needed: next write to s_val is after the next __syncthreads
    }
    __syncthreads();

    // softmax over the 20 extracted values (topv[0] is the row max)
    const float m = topv[0];
    float sum = 0.0f;
    #pragma unroll
    for (int i = 0; i < TOPK_K; i++) sum += expf(topv[i] - m);
    const float inv = 1.0f / sum;

    // write full row: zeros (vectorized), then scatter the 20 weights
    float4* orow4 = (float4*)(out + (size_t)row * N_NODES);
    const float4 z = make_float4(0.f, 0.f, 0.f, 0.f);
    #pragma unroll
    for (int i = t; i < N_NODES / 4; i += 256) orow4[i] = z;
    __syncthreads();
    if (t < TOPK_K)
        out[(size_t)row * N_NODES + topi[t]] = expf(topv[t] - m) * inv;
}

// ---------------------------------------------------------------------------
extern "C" void kernel_launch(void* const* d_in, const int* in_sizes, int n_in,
                              void* d_out, int out_size)
{
    const float* h           = (const float*)d_in[0];   // [8192, 512]
    const float* prior_adj   = (const float*)d_in[1];   // [8192, 8192]
    const float* W_q         = (const float*)d_in[2];   // [512, 512]
    const float* W_k         = (const float*)d_in[3];   // [512, 512]
    const float* prior_scale = (const float*)d_in[4];   // scalar
    float* out = (float*)d_out;                         // [8192, 8192]

    float* Qg = nullptr;
    float* Kg = nullptr;
    float* Lg = nullptr;
    cudaGetSymbolAddress((void**)&Qg, g_Q);
    cudaGetSymbolAddress((void**)&Kg, g_K);
    cudaGetSymbolAddress((void**)&Lg, g_logits);

    // Stage 1: Q = h @ W_q^T, K = h @ W_k^T  (fp32)
    {
        dim3 grid(DIM / 128, N_NODES / 128);
        gemm_nt_kernel<false><<<grid, 256>>>(h, W_q, Qg, nullptr, nullptr,
                                             N_NODES, DIM, DIM, 1.0f);
        gemm_nt_kernel<false><<<grid, 256>>>(h, W_k, Kg, nullptr, nullptr,
                                             N_NODES, DIM, DIM, 1.0f);
    }

    // Stage 2: logits = Q@K^T / sqrt(D) + prior_scale*prior, diagonal -> -inf
    {
        const float alpha = (float)(1.0 / sqrt((double)DIM));
        dim3 grid(N_NODES / 128, N_NODES / 128);
        gemm_nt_kernel<true><<<grid, 256>>>(Qg, Kg, Lg, prior_adj, prior_scale,
                                            N_NODES, N_NODES, DIM, alpha);
    }

    // Stage 3: per-row top-20 + softmax + full-row output write
    topk_softmax_kernel<<<N_NODES, 256>>>(Lg, out);
}

// round 5
// speedup vs baseline: 1.5672x; 1.5672x over previous
#include <cuda_runtime.h>
#include <cuda_bf16.h>
#include <math.h>
#include <stdint.h>

#define N_NODES 8192
#define DIM     512
#define TOPK_K  20
#define NCAND   32
#define K3      1536                       // 3 * DIM (split-bf16 concat)
#define ALPHA   0.044194173824159216f      // 1/sqrt(512) (approx path only)
#define SQRTD   22.62741699796952f         // fp32(sqrt(512)) (exact path: divide)

#define NEG_INF __int_as_float(0xff800000)

// ---------------- device scratch (static globals, no runtime alloc) --------
__device__ __nv_bfloat16 g_A[(size_t)N_NODES * K3];     // [Q_hi | Q_hi | Q_lo]
__device__ __nv_bfloat16 g_B[(size_t)N_NODES * K3];     // [K_hi | K_lo | K_hi]
__device__ float         g_Q[(size_t)N_NODES * DIM];    // exact fp32 Q
__device__ float         g_K[(size_t)N_NODES * DIM];    // exact fp32 K
__device__ float         g_logits[(size_t)N_NODES * N_NODES];

// ============================ PTX helpers ==================================
__device__ __forceinline__ uint32_t smem_u32(const void* p) {
    uint32_t a;
    asm("{ .reg .u64 t; cvta.to.shared.u64 t, %1; cvt.u32.u64 %0, t; }"
        : "=r"(a) : "l"(p));
    return a;
}
__device__ __forceinline__ void cp_async16(uint32_t dst, const void* src) {
    asm volatile("cp.async.cg.shared.global [%0], [%1], 16;" :: "r"(dst), "l"(src));
}
#define CP_COMMIT()   asm volatile("cp.async.commit_group;" ::: "memory")
#define CP_WAIT(N)    asm volatile("cp.async.wait_group %0;" :: "n"(N) : "memory")

#define LDSM_X4(r, addr)                                                       \
    asm volatile("ldmatrix.sync.aligned.m8n8.x4.shared.b16 {%0,%1,%2,%3}, [%4];" \
        : "=r"((r)[0]), "=r"((r)[1]), "=r"((r)[2]), "=r"((r)[3]) : "r"(addr))

__device__ __forceinline__ void mma16816(float* c, const uint32_t* a,
                                         const uint32_t* b) {
    asm volatile(
        "mma.sync.aligned.m16n8k16.row.col.f32.bf16.bf16.f32 "
        "{%0,%1,%2,%3}, {%4,%5,%6,%7}, {%8,%9}, {%0,%1,%2,%3};"
        : "+f"(c[0]), "+f"(c[1]), "+f"(c[2]), "+f"(c[3])
        : "r"(a[0]), "r"(a[1]), "r"(a[2]), "r"(a[3]), "r"(b[0]), "r"(b[1]));
}

// ===========================================================================
// Stage 1: projections.  C = h @ W^T (fp32 SGEMM, ascending-k accumulation).
// Epilogue writes fp32 Q/K AND split-bf16 operands per blockIdx.z.
// ===========================================================================
__global__ void __launch_bounds__(256, 2)
proj_kernel(const float* __restrict__ h, const float* __restrict__ W_q,
            const float* __restrict__ W_k)
{
    constexpr int BM = 128, BN = 128, BK = 8, TM = 8, TN = 8;
    constexpr int Kd = DIM;
    __shared__ float As[BK * BM];
    __shared__ float Bs[BK * BN];

    const int tid  = threadIdx.x;
    const int brow = blockIdx.y;
    const int bcol = blockIdx.x;
    const int z    = blockIdx.z;

    const float* A = h;
    const float* B = z == 0 ? W_q : W_k;

    const float* Ab = A + (size_t)brow * BM * Kd;
    const float* Bb = B + (size_t)bcol * BN * Kd;

    const int trow = tid / 16;
    const int tcol = tid % 16;
    const int innerRow = tid / 2;
    const int innerCol = tid % 2;

    float acc[TM][TN] = {};
    float regM[TM], regN[TN];

    for (int kt = 0; kt < Kd; kt += BK) {
        float4 a4 = *(const float4*)(Ab + (size_t)innerRow * Kd + kt + innerCol * 4);
        float4 b4 = *(const float4*)(Bb + (size_t)innerRow * Kd + kt + innerCol * 4);
        As[(innerCol * 4 + 0) * BM + innerRow] = a4.x;
        As[(innerCol * 4 + 1) * BM + innerRow] = a4.y;
        As[(innerCol * 4 + 2) * BM + innerRow] = a4.z;
        As[(innerCol * 4 + 3) * BM + innerRow] = a4.w;
        Bs[(innerCol * 4 + 0) * BN + innerRow] = b4.x;
        Bs[(innerCol * 4 + 1) * BN + innerRow] = b4.y;
        Bs[(innerCol * 4 + 2) * BN + innerRow] = b4.z;
        Bs[(innerCol * 4 + 3) * BN + innerRow] = b4.w;
        __syncthreads();

        #pragma unroll
        for (int k = 0; k < BK; k++) {
            #pragma unroll
            for (int i = 0; i < TM; i++) regM[i] = As[k * BM + trow * TM + i];
            #pragma unroll
            for (int j = 0; j < TN; j++) regN[j] = Bs[k * BN + tcol * TN + j];
            #pragma unroll
            for (int i = 0; i < TM; i++)
                #pragma unroll
                for (int j = 0; j < TN; j++)
                    acc[i][j] += regM[i] * regN[j];
        }
        __syncthreads();
    }

    __nv_bfloat16* dst = z == 0 ? g_A : g_B;
    float* dstf = z == 0 ? g_Q : g_K;
    #pragma unroll
    for (int i = 0; i < TM; i++) {
        const int gm = brow * BM + trow * TM + i;
        #pragma unroll
        for (int j = 0; j < TN; j += 2) {
            const int gn = bcol * BN + tcol * TN + j;
            float x0 = acc[i][j], x1 = acc[i][j + 1];
            *(float2*)(dstf + (size_t)gm * DIM + gn) = make_float2(x0, x1);
            __nv_bfloat16 h0 = __float2bfloat16(x0);
            __nv_bfloat16 h1 = __float2bfloat16(x1);
            __nv_bfloat16 l0 = __float2bfloat16(x0 - __bfloat162float(h0));
            __nv_bfloat16 l1 = __float2bfloat16(x1 - __bfloat162float(h1));
            __nv_bfloat162 hh; hh.x = h0; hh.y = h1;
            __nv_bfloat162 ll; ll.x = l0; ll.y = l1;
            size_t base = (size_t)gm * K3 + gn;
            if (z == 0) {   // A' = [Q_hi | Q_hi | Q_lo]
                *(__nv_bfloat162*)(dst + base)             = hh;
                *(__nv_bfloat162*)(dst + base + DIM)       = hh;
                *(__nv_bfloat162*)(dst + base + 2 * DIM)   = ll;
            } else {        // B' = [K_hi | K_lo | K_hi]
                *(__nv_bfloat162*)(dst + base)             = hh;
                *(__nv_bfloat162*)(dst + base + DIM)       = ll;
                *(__nv_bfloat162*)(dst + base + 2 * DIM)   = hh;
            }
        }
    }
}

// ===========================================================================
// Stage 2: approx logits = alpha * A' @ B'^T + ps * prior, diag -> -inf
// sm80-style HMMA GEMM: 128x128 tile, BK=64, 3-stage cp.async, SW128 smem.
// ===========================================================================
constexpr int G_STAGES = 3;
constexpr int G_NKT    = K3 / 64;            // 24 k-tiles
constexpr int G_ABYTES = 128 * 128;
constexpr int G_BBYTES = 128 * 128;
constexpr int G_PAD    = 1024;
constexpr int G_SMEM_TOTAL = G_PAD + G_STAGES * (G_ABYTES + G_BBYTES); // 99328

__device__ __forceinline__ void g2_load_tile(
    uint32_t sA, uint32_t sB, int kt,
    const __nv_bfloat16* Abase, const __nv_bfloat16* Bbase, int tid)
{
    #pragma unroll
    for (int i = 0; i < 8; i++) {
        const bool isA = i < 4;
        const int cc  = isA ? (tid + i * 256) : (tid + (i - 4) * 256);
        const int row = cc >> 3;
        const int kc  = cc & 7;
        const char* g = (const char*)((isA ? Abase : Bbase)
                          + (size_t)row * K3 + (size_t)kt * 64) + (kc << 4);
        uint32_t o = (uint32_t)(row << 7) + (uint32_t)(kc << 4);
        o ^= (o >> 3) & 0x70;                // SW128 swizzle
        cp_async16((isA ? sA : sB) + o, g);
    }
}

__global__ void __launch_bounds__(256, 2)
gemm2_kernel(const float* __restrict__ prior, const float* __restrict__ prior_scale)
{
    extern __shared__ char smem_raw[];
    uint32_t sbase = smem_u32(smem_raw);
    sbase = (sbase + (G_PAD - 1)) & ~(uint32_t)(G_PAD - 1);

    const int tid  = threadIdx.x;
    const int wid  = tid >> 5;
    const int lane = tid & 31;
    const int wm   = wid & 3;
    const int wn   = wid >> 2;
    const int bm   = blockIdx.y;
    const int bn   = blockIdx.x;

    const __nv_bfloat16* Abase = g_A + (size_t)bm * 128 * K3;
    const __nv_bfloat16* Bbase = g_B + (size_t)bn * 128 * K3;

    const uint32_t sA0 = sbase;
    const uint32_t sB0 = sbase + G_STAGES * G_ABYTES;

    float acc[2][8][4] = {};

    #pragma unroll
    for (int s = 0; s < G_STAGES - 1; s++) {
        g2_load_tile(sA0 + s * G_ABYTES, sB0 + s * G_BBYTES, s, Abase, Bbase, tid);
        CP_COMMIT();
    }

    for (int it = 0; it < G_NKT; it++) {
        CP_WAIT(G_STAGES - 2);
        __syncthreads();

        const int pf = it + G_STAGES - 1;
        if (pf < G_NKT) {
            const int s = pf % G_STAGES;
            g2_load_tile(sA0 + s * G_ABYTES, sB0 + s * G_BBYTES, pf,
                         Abase, Bbase, tid);
        }
        CP_COMMIT();

        const int s = it % G_STAGES;
        const uint32_t sA = sA0 + s * G_ABYTES;
        const uint32_t sB = sB0 + s * G_BBYTES;

        #pragma unroll
        for (int ks = 0; ks < 4; ks++) {
            uint32_t a[2][4];
            #pragma unroll
            for (int mi = 0; mi < 2; mi++) {
                const int row = wm * 32 + mi * 16 + (lane & 15);
                uint32_t o = (uint32_t)(row << 7) + (uint32_t)(ks << 5)
                           + (uint32_t)((lane >> 4) << 4);
                o ^= (o >> 3) & 0x70;
                LDSM_X4(a[mi], sA + o);
            }
            uint32_t b[4][4];
            #pragma unroll
            for (int np = 0; np < 4; np++) {
                const int row = wn * 64 + np * 16 + (lane & 7) + ((lane >> 4) << 3);
                uint32_t o = (uint32_t)(row << 7) + (uint32_t)(ks << 5)
                           + (uint32_t)(((lane >> 3) & 1) << 4);
                o ^= (o >> 3) & 0x70;
                LDSM_X4(b[np], sB + o);
            }
            #pragma unroll
            for (int mi = 0; mi < 2; mi++)
                #pragma unroll
                for (int nj = 0; nj < 8; nj++)
                    mma16816(acc[mi][nj], a[mi], &b[nj >> 1][(nj & 1) * 2]);
        }
    }

    const float ps = prior_scale[0];
    #pragma unroll
    for (int mi = 0; mi < 2; mi++) {
        const int r0 = bm * 128 + wm * 32 + mi * 16 + (lane >> 2);
        const int r1 = r0 + 8;
        #pragma unroll
        for (int nj = 0; nj < 8; nj++) {
            const int c = bn * 128 + wn * 64 + nj * 8 + ((lane & 3) << 1);
            const float2 p0 = *(const float2*)(prior + (size_t)r0 * N_NODES + c);
            float2 o0;
            o0.x = acc[mi][nj][0] * ALPHA + ps * p0.x;
            o0.y = acc[mi][nj][1] * ALPHA + ps * p0.y;
            if (r0 == c)     o0.x = NEG_INF;
            if (r0 == c + 1) o0.y = NEG_INF;
            *(float2*)(g_logits + (size_t)r0 * N_NODES + c) = o0;

            const float2 p1 = *(const float2*)(prior + (size_t)r1 * N_NODES + c);
            float2 o1;
            o1.x = acc[mi][nj][2] * ALPHA + ps * p1.x;
            o1.y = acc[mi][nj][3] * ALPHA + ps * p1.y;
            if (r1 == c)     o1.x = NEG_INF;
            if (r1 == c + 1) o1.y = NEG_INF;
            *(float2*)(g_logits + (size_t)r1 * N_NODES + c) = o1;
        }
    }
}

// ===========================================================================
// Stage 3: top-32 candidates from approx logits -> exact rescoring with
// ASCENDING-K SERIAL fp32 FMA (matches cuBLAS/reference accumulation order)
// -> exact top-20 (tie-break: lower column index) + softmax + row write.
// ===========================================================================
__global__ void __launch_bounds__(256)
topk_softmax_kernel(const float* __restrict__ logits,
                    const float* __restrict__ Q,
                    const float* __restrict__ Km,
                    const float* __restrict__ prior,
                    const float* __restrict__ prior_scale,
                    float* __restrict__ out)
{
    const int row  = blockIdx.x;
    const int t    = threadIdx.x;
    const int wid  = t >> 5;
    const int lane = t & 31;
    const float* lrow = logits + (size_t)row * N_NODES;

    float v[32];
    #pragma unroll
    for (int i = 0; i < 32; i++)
        v[i] = lrow[t + 256 * i];

    // zero the output row early (ordered before scatter by later syncthreads)
    float4* orow4 = (float4*)(out + (size_t)row * N_NODES);
    const float4 zz = make_float4(0.f, 0.f, 0.f, 0.f);
    #pragma unroll
    for (int i = t; i < N_NODES / 4; i += 256) orow4[i] = zz;

    __shared__ float qrow[DIM];
    qrow[t]       = Q[(size_t)row * DIM + t];
    qrow[t + 256] = Q[(size_t)row * DIM + t + 256];

    // cached per-thread local argmax
    float bv = NEG_INF;
    int   bi = 0;
    #pragma unroll
    for (int i = 0; i < 32; i++)
        if (v[i] > bv) { bv = v[i]; bi = i; }
    int bj = t + 256 * bi;

    __shared__ float s_val[8];
    __shared__ int   s_idx[8];
    __shared__ int   candi[NCAND];
    __shared__ float exactv[NCAND];
    __shared__ int   s_winner;

    for (int it = 0; it < NCAND; it++) {
        float wv = bv;
        int   wj = bj;
        #pragma unroll
        for (int o = 16; o > 0; o >>= 1) {
            float ov = __shfl_down_sync(0xffffffffu, wv, o);
            int   oj = __shfl_down_sync(0xffffffffu, wj, o);
            if (ov > wv) { wv = ov; wj = oj; }
        }
        if (lane == 0) { s_val[wid] = wv; s_idx[wid] = wj; }
        __syncthreads();

        if (t == 0) {
            float best = s_val[0]; int bidx = s_idx[0];
            #pragma unroll
            for (int w = 1; w < 8; w++)
                if (s_val[w] > best) { best = s_val[w]; bidx = s_idx[w]; }
            candi[it]  = bidx;
            s_winner   = bidx;
        }
        __syncthreads();

        const int widx = s_winner;
        if ((widx & 255) == t) {
            v[widx >> 8] = NEG_INF;
            bv = NEG_INF; bi = 0;
            #pragma unroll
            for (int i = 0; i < 32; i++)
                if (v[i] > bv) { bv = v[i]; bi = i; }
            bj = t + 256 * bi;
        }
        __syncthreads();
    }

    // ---- exact rescoring: one thread per candidate, strictly serial
    //      ascending-k fp32 FMA chain (cuBLAS-order-compatible) ----
    if (t < NCAND) {
        const int cand = candi[t];
        const float* krow = Km + (size_t)cand * DIM;
        float acc = 0.0f;
        #pragma unroll 8
        for (int k = 0; k < DIM; k++)
            acc = fmaf(qrow[k], krow[k], acc);
        float val = acc / SQRTD;                 // matches jax's divide
        val = val + prior_scale[0] * prior[(size_t)row * N_NODES + cand];
        exactv[t] = val;
    }
    __syncthreads();   // also orders the row-zeroing before the scatter

    // ---- warp 0: exact top-20 of 32 (ties -> lower column index),
    //      softmax, scatter ----
    if (wid == 0) {
        float val = exactv[lane];
        int   col = candi[lane];
        float selv = NEG_INF;
        int   seli = 0;
        #pragma unroll
        for (int it = 0; it < TOPK_K; it++) {
            float m = val;
            int   j = col;
            #pragma unroll
            for (int o = 16; o > 0; o >>= 1) {
                float om = __shfl_xor_sync(0xffffffffu, m, o);
                int   oj = __shfl_xor_sync(0xffffffffu, j, o);
                if (om > m || (om == m && oj < j)) { m = om; j = oj; }
            }
            if (lane == it) { selv = m; seli = j; }
            if (val == m && col == j) val = NEG_INF;   // remove winner (col unique)
        }
        const float mx = __shfl_sync(0xffffffffu, selv, 0);
        float e = (lane < TOPK_K) ? expf(selv - mx) : 0.0f;
        float s = e;
        #pragma unroll
        for (int o = 16; o > 0; o >>= 1)
            s += __shfl_xor_sync(0xffffffffu, s, o);
        if (lane < TOPK_K)
            out[(size_t)row * N_NODES + seli] = e / s;
    }
}

// ===========================================================================
extern "C" void kernel_launch(void* const* d_in, const int* in_sizes, int n_in,
                              void* d_out, int out_size)
{
    const float* h           = (const float*)d_in[0];   // [8192, 512]
    const float* prior_adj   = (const float*)d_in[1];   // [8192, 8192]
    const float* W_q         = (const float*)d_in[2];   // [512, 512]
    const float* W_k         = (const float*)d_in[3];   // [512, 512]
    const float* prior_scale = (const float*)d_in[4];   // scalar
    float* out = (float*)d_out;                         // [8192, 8192]

    float *Lg = nullptr, *Qg = nullptr, *Kg = nullptr;
    cudaGetSymbolAddress((void**)&Lg, g_logits);
    cudaGetSymbolAddress((void**)&Qg, g_Q);
    cudaGetSymbolAddress((void**)&Kg, g_K);

    // Stage 1: projections + fp32 Q/K + split-bf16 pack
    proj_kernel<<<dim3(DIM / 128, N_NODES / 128, 2), 256>>>(h, W_q, W_k);

    // Stage 2: HMMA split-bf16 GEMM with fused prior + diag epilogue
    cudaFuncSetAttribute(gemm2_kernel,
                         cudaFuncAttributeMaxDynamicSharedMemorySize, G_SMEM_TOTAL);
    gemm2_kernel<<<dim3(N_NODES / 128, N_NODES / 128), 256, G_SMEM_TOTAL>>>(
        prior_adj, prior_scale);

    // Stage 3: top-32 candidates -> serial-order exact rescoring -> top-20
    topk_softmax_kernel<<<N_NODES, 256>>>(Lg, Qg, Kg, prior_adj, prior_scale, out);
}